// round 1
// baseline (speedup 1.0000x reference)
#include <cuda_runtime.h>
#include <math.h>

// ---------------- static config ----------------
constexpr int NXg = 432, NYg = 496, Bb = 4;
constexpr int Hh = 248, Ww = 216;
constexpr int HW = Hh * Ww;            // 53568
constexpr int C_IN = 384, NDF = 16;
constexpr int NYNX = NYg * NXg;        // 214272
constexpr int KS = 15, RR = 7;
constexpr int NBX = (HW + 255) / 256;  // 210
constexpr int NB_TOT = NBX * Bb;       // 840
constexpr float BN_EPS = 1e-3f;
constexpr int CNT = Bb * HW;           // 214272
constexpr int PL4 = HW / 4;            // 13392

// ---------------- scratch (static, no allocation) ----------------
__device__ int   d_hist[Bb * NYNX];
__device__ float d_tmp [Bb * NYNX];
__device__ float d_dm  [Bb * NYNX];
__device__ int   d_max [Bb];
__device__ float d_gauss[KS];
__device__ float d_dmr [Bb * HW];
__device__ float d_buf1[Bb * 8  * HW];
__device__ float d_buf2[Bb * 16 * HW];
__device__ float d_part1[16 * NB_TOT];
__device__ float d_part2[32 * NB_TOT];
__device__ float d_sc1[8],  d_sh1[8];
__device__ float d_sc2[16], d_sh2[16];

// ---------------- kernels ----------------
__global__ void k_init() {
    int i = blockIdx.x * blockDim.x + threadIdx.x;
    int stride = gridDim.x * blockDim.x;
    for (int p = i; p < Bb * NYNX; p += stride) d_hist[p] = 0;
    if (i < Bb) d_max[i] = 0;
    if (i == 0) {
        float g[KS]; float s = 0.f;
        #pragma unroll
        for (int k = 0; k < KS; k++) {
            float c = (float)(k - RR);
            g[k] = expf(-(c * c) / 78.125f);   // 2*sigma^2, sigma=6.25
            s += g[k];
        }
        #pragma unroll
        for (int k = 0; k < KS; k++) d_gauss[k] = g[k] / s;
    }
}

__global__ void k_hist(const float* __restrict__ pts, int n) {
    int i = blockIdx.x * blockDim.x + threadIdx.x;
    if (i >= n) return;
    float b_f = pts[i * 5 + 0];
    float px  = pts[i * 5 + 1];
    float py  = pts[i * 5 + 2];
    int b  = (int)b_f;
    int xi = (int)__fdiv_rn(px - 0.0f, 0.16f);      // match f32 division exactly
    int yi = (int)__fdiv_rn(py - (-39.68f), 0.16f);
    xi = min(max(xi, 0), NXg - 1);
    yi = min(max(yi, 0), NYg - 1);
    atomicAdd(&d_hist[b * NYNX + yi * NXg + xi], 1);
}

// vertical blur (zero padding), int hist -> float tmp
__global__ void k_vblur() {
    int p = blockIdx.x * 256 + threadIdx.x;
    int b = blockIdx.y;
    if (p >= NYNX) return;
    int y = p / NXg, x = p - y * NXg;
    const int* h = d_hist + b * NYNX;
    float acc = 0.f;
    #pragma unroll
    for (int j = 0; j < KS; j++) {
        int yy = y + j - RR;
        if (yy >= 0 && yy < NYg) acc = fmaf(d_gauss[j], (float)h[yy * NXg + x], acc);
    }
    d_tmp[b * NYNX + p] = acc;
}

// horizontal blur (zero padding) + per-batch max reduce
__global__ void k_hblur() {
    __shared__ float red[256];
    int tid = threadIdx.x;
    int p = blockIdx.x * 256 + tid;
    int b = blockIdx.y;
    float acc = 0.f;
    if (p < NYNX) {
        int y = p / NXg, x = p - y * NXg;
        const float* t = d_tmp + b * NYNX + y * NXg;
        #pragma unroll
        for (int j = 0; j < KS; j++) {
            int xx = x + j - RR;
            if (xx >= 0 && xx < NXg) acc = fmaf(d_gauss[j], t[xx], acc);
        }
        d_dm[b * NYNX + p] = acc;
    }
    red[tid] = acc;
    __syncthreads();
    for (int s = 128; s > 0; s >>= 1) {
        if (tid < s) red[tid] = fmaxf(red[tid], red[tid + s]);
        __syncthreads();
    }
    if (tid == 0) atomicMax(&d_max[b], __float_as_int(red[0]));  // values >= 0
}

// antialiased 2x downsample (jax.image.resize linear, antialias=True) + /max
__global__ void k_resize() {
    int p = blockIdx.x * 256 + threadIdx.x;
    int b = blockIdx.y;
    if (p >= HW) return;
    int y = p / Ww, x = p - y * Ww;

    float wy[4], wx[4]; int ry[4], rx[4];
    float sy = 0.f, sx = 0.f;
    #pragma unroll
    for (int j = 0; j < 4; j++) {
        float w = (j == 0 || j == 3) ? 0.25f : 0.75f;
        int r = 2 * y - 1 + j;
        bool v = (r >= 0) && (r < NYg);
        wy[j] = v ? w : 0.f; ry[j] = v ? r : 0; sy += wy[j];
        int c = 2 * x - 1 + j;
        bool vc = (c >= 0) && (c < NXg);
        wx[j] = vc ? w : 0.f; rx[j] = vc ? c : 0; sx += wx[j];
    }
    #pragma unroll
    for (int j = 0; j < 4; j++) { wy[j] /= sy; wx[j] /= sx; }

    const float* dm = d_dm + b * NYNX;
    float acc = 0.f;
    #pragma unroll
    for (int jy = 0; jy < 4; jy++) {
        const float* row = dm + ry[jy] * NXg;
        float r = 0.f;
        #pragma unroll
        for (int jx = 0; jx < 4; jx++) r = fmaf(wx[jx], row[rx[jx]], r);
        acc = fmaf(wy[jy], r, acc);
    }
    float mx = __int_as_float(d_max[b]);
    d_dmr[b * HW + p] = (mx > 0.f) ? __fdiv_rn(acc, mx) : acc;
}

// conv3x3 1->8 (zero pad) + per-block partial sums for BN1
__global__ void k_conv1(const float* __restrict__ w1) {
    __shared__ float sw[72];
    __shared__ float wred[16 * 8];
    int tid = threadIdx.x;
    if (tid < 72) sw[tid] = w1[tid];
    __syncthreads();

    int p = blockIdx.x * 256 + tid;
    int b = blockIdx.y;
    float acc[8] = {0.f,0.f,0.f,0.f,0.f,0.f,0.f,0.f};
    if (p < HW) {
        int y = p / Ww, x = p - y * Ww;
        const float* src = d_dmr + b * HW;
        #pragma unroll
        for (int ky = 0; ky < 3; ky++) {
            int yy = y + ky - 1;
            if (yy < 0 || yy >= Hh) continue;
            #pragma unroll
            for (int kx = 0; kx < 3; kx++) {
                int xx = x + kx - 1;
                if (xx < 0 || xx >= Ww) continue;
                float v = src[yy * Ww + xx];
                int wi = ky * 3 + kx;
                #pragma unroll
                for (int c = 0; c < 8; c++) acc[c] = fmaf(v, sw[c * 9 + wi], acc[c]);
            }
        }
        float* dst = d_buf1 + (size_t)(b * 8) * HW + p;
        #pragma unroll
        for (int c = 0; c < 8; c++) dst[c * HW] = acc[c];
    }
    // deterministic fixed-tree stats: 16 quantities (sum, sumsq per channel)
    int lane = tid & 31, wid = tid >> 5;
    int blk = blockIdx.y * gridDim.x + blockIdx.x;
    #pragma unroll
    for (int q = 0; q < 16; q++) {
        int c = q >> 1;
        float v = (q & 1) ? acc[c] * acc[c] : acc[c];
        #pragma unroll
        for (int s = 16; s > 0; s >>= 1) v += __shfl_down_sync(0xffffffffu, v, s);
        if (lane == 0) wred[q * 8 + wid] = v;
    }
    __syncthreads();
    if (tid < 16) {
        float s = 0.f;
        #pragma unroll
        for (int w = 0; w < 8; w++) s += wred[tid * 8 + w];
        d_part1[tid * NB_TOT + blk] = s;
    }
}

__global__ void k_stats1(const float* __restrict__ g, const float* __restrict__ be) {
    int tid = threadIdx.x;
    __shared__ float sums[16];
    if (tid < 16) {
        float s = 0.f;
        for (int i = 0; i < NB_TOT; i++) s += d_part1[tid * NB_TOT + i];
        sums[tid] = s;
    }
    __syncthreads();
    if (tid < 8) {
        float mean = sums[tid * 2] / (float)CNT;
        float var  = sums[tid * 2 + 1] / (float)CNT - mean * mean;
        float inv  = rsqrtf(var + BN_EPS);
        float sc   = g[tid] * inv;
        d_sc1[tid] = sc;
        d_sh1[tid] = be[tid] - mean * sc;
    }
}

// bn1+relu applied on the fly, conv3x3 8->16 (zero pad on h), partial stats for BN2
__global__ void k_conv2(const float* __restrict__ w2) {
    __shared__ float sw[1152];
    __shared__ float ssc[8], ssh[8];
    __shared__ float wred[32 * 8];
    int tid = threadIdx.x;
    for (int i = tid; i < 1152; i += 256) sw[i] = w2[i];
    if (tid < 8) { ssc[tid] = d_sc1[tid]; ssh[tid] = d_sh1[tid]; }
    __syncthreads();

    int p = blockIdx.x * 256 + tid;
    int b = blockIdx.y;
    float acc[16];
    #pragma unroll
    for (int i = 0; i < 16; i++) acc[i] = 0.f;
    if (p < HW) {
        int y = p / Ww, x = p - y * Ww;
        const float* src = d_buf1 + (size_t)(b * 8) * HW;
        #pragma unroll
        for (int ky = 0; ky < 3; ky++) {
            int yy = y + ky - 1;
            if (yy < 0 || yy >= Hh) continue;
            #pragma unroll
            for (int kx = 0; kx < 3; kx++) {
                int xx = x + kx - 1;
                if (xx < 0 || xx >= Ww) continue;
                int off = yy * Ww + xx;
                int wi = ky * 3 + kx;
                float hbuf[8];
                #pragma unroll
                for (int c = 0; c < 8; c++) {
                    float v = src[c * HW + off];
                    hbuf[c] = fmaxf(fmaf(v, ssc[c], ssh[c]), 0.f);
                }
                #pragma unroll
                for (int oc = 0; oc < 16; oc++) {
                    #pragma unroll
                    for (int ic = 0; ic < 8; ic++)
                        acc[oc] = fmaf(hbuf[ic], sw[(oc * 8 + ic) * 9 + wi], acc[oc]);
                }
            }
        }
        float* dst = d_buf2 + (size_t)(b * 16) * HW + p;
        #pragma unroll
        for (int oc = 0; oc < 16; oc++) dst[oc * HW] = acc[oc];
    }
    int lane = tid & 31, wid = tid >> 5;
    int blk = blockIdx.y * gridDim.x + blockIdx.x;
    #pragma unroll
    for (int q = 0; q < 32; q++) {
        int c = q >> 1;
        float v = (q & 1) ? acc[c] * acc[c] : acc[c];
        #pragma unroll
        for (int s = 16; s > 0; s >>= 1) v += __shfl_down_sync(0xffffffffu, v, s);
        if (lane == 0) wred[q * 8 + wid] = v;
    }
    __syncthreads();
    if (tid < 32) {
        float s = 0.f;
        #pragma unroll
        for (int w = 0; w < 8; w++) s += wred[tid * 8 + w];
        d_part2[tid * NB_TOT + blk] = s;
    }
}

__global__ void k_stats2(const float* __restrict__ g, const float* __restrict__ be) {
    int tid = threadIdx.x;
    __shared__ float sums[32];
    if (tid < 32) {
        float s = 0.f;
        for (int i = 0; i < NB_TOT; i++) s += d_part2[tid * NB_TOT + i];
        sums[tid] = s;
    }
    __syncthreads();
    if (tid < 16) {
        float mean = sums[tid * 2] / (float)CNT;
        float var  = sums[tid * 2 + 1] / (float)CNT - mean * mean;
        float inv  = rsqrtf(var + BN_EPS);
        float sc   = g[tid] * inv;
        d_sc2[tid] = sc;
        d_sh2[tid] = be[tid] - mean * sc;
    }
}

// density channels: bn2+relu, written to out channels [384, 400)
__global__ void k_writedens(float* __restrict__ out) {
    constexpr int N4 = Bb * NDF * PL4;    // 857088
    int i = blockIdx.x * 256 + threadIdx.x;
    if (i >= N4) return;
    int b = i / (NDF * PL4);
    int r = i - b * (NDF * PL4);
    int c = r / PL4;
    float4 v = reinterpret_cast<const float4*>(d_buf2)[i];
    float sc = d_sc2[c], sh = d_sh2[c];
    v.x = fmaxf(fmaf(v.x, sc, sh), 0.f);
    v.y = fmaxf(fmaf(v.y, sc, sh), 0.f);
    v.z = fmaxf(fmaf(v.z, sc, sh), 0.f);
    v.w = fmaxf(fmaf(v.w, sc, sh), 0.f);
    reinterpret_cast<float4*>(out)[(size_t)(b * (C_IN + NDF) + C_IN) * PL4 + (r - c * PL4) + (size_t)c * PL4] = v;
}

// passthrough copy of spatial features into out channels [0, 384)
__global__ void k_copy(const float4* __restrict__ sp, float4* __restrict__ out) {
    constexpr int CB4 = C_IN * PL4;       // 5142528 float4 per batch
    int i = blockIdx.x * 256 + threadIdx.x;
    if (i >= Bb * CB4) return;
    int b = i / CB4;
    int r = i - b * CB4;
    out[(size_t)b * (C_IN + NDF) * PL4 + r] = sp[i];
}

// ---------------- launch ----------------
extern "C" void kernel_launch(void* const* d_in, const int* in_sizes, int n_in,
                              void* d_out, int out_size) {
    const float* spatial = (const float*)d_in[0];
    const float* points  = (const float*)d_in[1];
    const float* w1 = (const float*)d_in[2];
    const float* g1 = (const float*)d_in[3];
    const float* b1 = (const float*)d_in[4];
    const float* w2 = (const float*)d_in[5];
    const float* g2 = (const float*)d_in[6];
    const float* b2 = (const float*)d_in[7];
    float* out = (float*)d_out;
    int npts = in_sizes[1] / 5;

    k_init<<<512, 256>>>();
    k_hist<<<(npts + 255) / 256, 256>>>(points, npts);
    dim3 gb((NYNX + 255) / 256, Bb);
    k_vblur<<<gb, 256>>>();
    k_hblur<<<gb, 256>>>();
    dim3 gh(NBX, Bb);
    k_resize<<<gh, 256>>>();
    k_conv1<<<gh, 256>>>(w1);
    k_stats1<<<1, 64>>>(g1, b1);
    k_conv2<<<gh, 256>>>(w2);
    k_stats2<<<1, 64>>>(g2, b2);
    k_writedens<<<(Bb * NDF * PL4 + 255) / 256, 256>>>(out);
    k_copy<<<(Bb * C_IN * PL4 + 255) / 256, 256>>>(
        (const float4*)spatial, (float4*)out);
}